// round 2
// baseline (speedup 1.0000x reference)
#include <cuda_runtime.h>
#include <math.h>

#define B_ 64
#define S_ 512
#define D_ 512
#define H_ 1024

// Scratch (device globals: allocation-free rule)
__device__ float g_H[2][B_ * H_];                 // double-buffered hidden state
__device__ float g_C[B_ * H_];                    // cell state
__device__ float g_outs[(size_t)S_ * B_ * H_];    // all hidden outputs [s][b][h]

// ---------------------------------------------------------------------------
// init: load H0 / C0 into state buffers
// ---------------------------------------------------------------------------
__global__ void lstm_init(const float* __restrict__ H0, const float* __restrict__ C0) {
    int i = blockIdx.x * blockDim.x + threadIdx.x;
    if (i < B_ * H_) {
        g_H[0][i] = H0[i];
        g_C[i]    = C0[i];
    }
}

// ---------------------------------------------------------------------------
// One LSTM step, fully fused:
//   g[b, 4H] = x_s[b, :] @ Wx(4H) + H_s[b, :] @ Wh(4H) + bias
//   gates -> C, H update, H also written to g_outs[s]
//
// Grid: 128 blocks (h-tile of 8 columns each), 128 threads.
// Thread t owns batch b = t>>1 and 4 h-columns (hh = (t&1)*4), for all 4 gates
// => 16 fp32 accumulators. K loop = 512 (x part) + 1024 (H part), tiled by 32,
// with register prefetch to hide global/L2 latency.
// ---------------------------------------------------------------------------

struct Pref {
    float4 pa[4];
    float4 pw0, pw1;
};

__device__ __forceinline__ void do_prefetch(
    Pref& p, const float* __restrict__ Abase, size_t astride,
    const float* __restrict__ WA, const float* __restrict__ WB,
    int k0, int t, int kkw, int wcol)
{
#pragma unroll
    for (int i = 0; i < 4; i++) {
        int idx = t + i * 128;
        int row = idx >> 3;
        int c4  = idx & 7;
        p.pa[i] = *(const float4*)(Abase + (size_t)row * astride + k0 + c4 * 4);
    }
    p.pw0 = *(const float4*)(WA + (size_t)(k0 + kkw) * H_ + wcol);
    p.pw1 = *(const float4*)(WB + (size_t)(k0 + kkw) * H_ + wcol);
}

__device__ __forceinline__ void store_smem(
    const Pref& p, float* __restrict__ sA, float* __restrict__ sW,
    int t, int gsel, int kkw, int q2w)
{
#pragma unroll
    for (int i = 0; i < 4; i++) {
        int idx = t + i * 128;
        int row = idx >> 3;
        int c4  = idx & 7;
        sA[row * 33 + c4 * 4 + 0] = p.pa[i].x;
        sA[row * 33 + c4 * 4 + 1] = p.pa[i].y;
        sA[row * 33 + c4 * 4 + 2] = p.pa[i].z;
        sA[row * 33 + c4 * 4 + 3] = p.pa[i].w;
    }
    *(float4*)&sW[((gsel    ) * 32 + kkw) * 8 + q2w * 4] = p.pw0;
    *(float4*)&sW[((gsel + 2) * 32 + kkw) * 8 + q2w * 4] = p.pw1;
}

__device__ __forceinline__ void compute_chunk(
    const float* __restrict__ sA, const float* __restrict__ sW,
    int b, int hh, float acc[16])
{
#pragma unroll
    for (int kk = 0; kk < 32; kk++) {
        float a = sA[b * 33 + kk];
        float4 wi = *(const float4*)&sW[(0 * 32 + kk) * 8 + hh];
        float4 wf = *(const float4*)&sW[(1 * 32 + kk) * 8 + hh];
        float4 wo = *(const float4*)&sW[(2 * 32 + kk) * 8 + hh];
        float4 wc = *(const float4*)&sW[(3 * 32 + kk) * 8 + hh];
        acc[0]  += a * wi.x;  acc[1]  += a * wi.y;  acc[2]  += a * wi.z;  acc[3]  += a * wi.w;
        acc[4]  += a * wf.x;  acc[5]  += a * wf.y;  acc[6]  += a * wf.z;  acc[7]  += a * wf.w;
        acc[8]  += a * wo.x;  acc[9]  += a * wo.y;  acc[10] += a * wo.z;  acc[11] += a * wo.w;
        acc[12] += a * wc.x;  acc[13] += a * wc.y;  acc[14] += a * wc.z;  acc[15] += a * wc.w;
    }
}

__device__ __forceinline__ float sigmoidf_(float x) {
    return 1.0f / (1.0f + expf(-x));
}

__global__ void __launch_bounds__(128) lstm_step(
    const float* __restrict__ x, int s, int cur,
    const float* __restrict__ Wxi, const float* __restrict__ Wxf,
    const float* __restrict__ Wxo, const float* __restrict__ Wxc,
    const float* __restrict__ Whi, const float* __restrict__ Whf,
    const float* __restrict__ Who, const float* __restrict__ Whc,
    const float* __restrict__ bi,  const float* __restrict__ bf,
    const float* __restrict__ bo,  const float* __restrict__ bc)
{
    __shared__ __align__(16) float sA[B_ * 33];      // activations tile, padded
    __shared__ __align__(16) float sW[4 * 32 * 8];   // [gate][kk][8]

    const int t  = threadIdx.x;
    const int h0 = blockIdx.x * 8;
    const int b  = t >> 1;
    const int hh = (t & 1) * 4;

    // per-thread loader coordinates (fixed)
    const int gsel = t >> 6;          // 0/1 -> gates (0,1) for pw0, (2,3) for pw1
    const int kkw  = (t & 63) >> 1;   // 0..31
    const int q2w  = t & 1;           // which float4 of the 8-wide h tile
    const int wcol = h0 + q2w * 4;

    float acc[16];
#pragma unroll
    for (int i = 0; i < 16; i++) acc[i] = 0.0f;

    Pref p;

    // ---- Phase 1: x part. A row b = x[b*S*D + s*D + k]  (K = 512) ----
    {
        const float* Ab = x + (size_t)s * D_;
        const size_t astride = (size_t)S_ * D_;
        const float* WA = gsel ? Wxf : Wxi;
        const float* WB = gsel ? Wxc : Wxo;
        do_prefetch(p, Ab, astride, WA, WB, 0, t, kkw, wcol);
        for (int c = 0; c < 16; c++) {
            __syncthreads();
            store_smem(p, sA, sW, t, gsel, kkw, q2w);
            __syncthreads();
            if (c < 15)
                do_prefetch(p, Ab, astride, WA, WB, (c + 1) * 32, t, kkw, wcol);
            compute_chunk(sA, sW, b, hh, acc);
        }
    }

    // ---- Phase 2: H part. A row b = Hs[b*H + k]  (K = 1024) ----
    {
        const float* Ab = g_H[cur];
        const size_t astride = H_;
        const float* WA = gsel ? Whf : Whi;
        const float* WB = gsel ? Whc : Who;
        do_prefetch(p, Ab, astride, WA, WB, 0, t, kkw, wcol);
        for (int c = 0; c < 32; c++) {
            __syncthreads();
            store_smem(p, sA, sW, t, gsel, kkw, q2w);
            __syncthreads();
            if (c < 31)
                do_prefetch(p, Ab, astride, WA, WB, (c + 1) * 32, t, kkw, wcol);
            compute_chunk(sA, sW, b, hh, acc);
        }
    }

    // ---- Epilogue: gates -> C, H ----
    const int h = h0 + hh;
    float4 bvi = *(const float4*)(bi + h);
    float4 bvf = *(const float4*)(bf + h);
    float4 bvo = *(const float4*)(bo + h);
    float4 bvc = *(const float4*)(bc + h);

    float gi[4], gf[4], go[4], gc[4];
    gi[0] = acc[0]  + bvi.x; gi[1] = acc[1]  + bvi.y; gi[2] = acc[2]  + bvi.z; gi[3] = acc[3]  + bvi.w;
    gf[0] = acc[4]  + bvf.x; gf[1] = acc[5]  + bvf.y; gf[2] = acc[6]  + bvf.z; gf[3] = acc[7]  + bvf.w;
    go[0] = acc[8]  + bvo.x; go[1] = acc[9]  + bvo.y; go[2] = acc[10] + bvo.z; go[3] = acc[11] + bvo.w;
    gc[0] = acc[12] + bvc.x; gc[1] = acc[13] + bvc.y; gc[2] = acc[14] + bvc.z; gc[3] = acc[15] + bvc.w;

    float4 Cs = *(const float4*)&g_C[b * H_ + h];
    float Csv[4] = {Cs.x, Cs.y, Cs.z, Cs.w};

    float4 Cn, Hn;
    float* Cnp = &Cn.x;
    float* Hnp = &Hn.x;
#pragma unroll
    for (int j = 0; j < 4; j++) {
        float iv = sigmoidf_(gi[j]);
        float fv = sigmoidf_(gf[j]);
        float ov = sigmoidf_(go[j]);
        float cv = tanhf(gc[j]);
        float cn = fv * Csv[j] + iv * cv;
        Cnp[j] = cn;
        Hnp[j] = ov * tanhf(cn);
    }

    *(float4*)&g_C[b * H_ + h]            = Cn;
    *(float4*)&g_H[cur ^ 1][b * H_ + h]   = Hn;
    *(float4*)&g_outs[((size_t)s * B_ + b) * H_ + h] = Hn;
}

// ---------------------------------------------------------------------------
// fc: pred[b,s] = outs[s][b][:] . fc_W + fc_b   (one warp per (s,b))
// ---------------------------------------------------------------------------
__global__ void fc_kernel(const float* __restrict__ fcW,
                          const float* __restrict__ fcb,
                          float* __restrict__ pred)
{
    int gw   = (blockIdx.x * blockDim.x + threadIdx.x) >> 5;
    int lane = threadIdx.x & 31;
    if (gw >= B_ * S_) return;
    int s = gw >> 6;     // consecutive warps share s -> coalesced rows
    int b = gw & 63;
    const float* row = g_outs + ((size_t)s * B_ + b) * H_;
    float sum = 0.0f;
#pragma unroll 4
    for (int hcol = lane; hcol < H_; hcol += 32)
        sum += row[hcol] * fcW[hcol];
#pragma unroll
    for (int o = 16; o; o >>= 1)
        sum += __shfl_down_sync(0xFFFFFFFFu, sum, o);
    if (lane == 0)
        pred[(size_t)b * S_ + s] = sum + fcb[0];
}

// ---------------------------------------------------------------------------
// finalize: append Hf, Cf after pred (guarded by out_size)
// ---------------------------------------------------------------------------
__global__ void finalize_kernel(float* __restrict__ out, int out_size) {
    int i = blockIdx.x * blockDim.x + threadIdx.x;
    if (i >= B_ * H_) return;
    const int PRED = B_ * S_;           // 32768
    if (out_size >= PRED + B_ * H_)
        out[PRED + i] = g_H[0][i];      // after 512 steps final H sits in buffer 0
    if (out_size >= PRED + 2 * B_ * H_)
        out[PRED + B_ * H_ + i] = g_C[i];
}

// ---------------------------------------------------------------------------
extern "C" void kernel_launch(void* const* d_in, const int* in_sizes, int n_in,
                              void* d_out, int out_size)
{
    const float* inputs = (const float*)d_in[0];
    const float* H0     = (const float*)d_in[1];
    const float* C0     = (const float*)d_in[2];
    const float* Wxi = (const float*)d_in[3];
    const float* Whi = (const float*)d_in[4];
    const float* bi  = (const float*)d_in[5];
    const float* Wxf = (const float*)d_in[6];
    const float* Whf = (const float*)d_in[7];
    const float* bf  = (const float*)d_in[8];
    const float* Wxo = (const float*)d_in[9];
    const float* Who = (const float*)d_in[10];
    const float* bo  = (const float*)d_in[11];
    const float* Wxc = (const float*)d_in[12];
    const float* Whc = (const float*)d_in[13];
    const float* bc  = (const float*)d_in[14];
    const float* fcW = (const float*)d_in[15];
    const float* fcb = (const float*)d_in[16];
    float* out = (float*)d_out;

    lstm_init<<<(B_ * H_ + 255) / 256, 256>>>(H0, C0);

    for (int s = 0; s < S_; s++) {
        lstm_step<<<H_ / 8, 128>>>(inputs, s, s & 1,
                                   Wxi, Wxf, Wxo, Wxc,
                                   Whi, Whf, Who, Whc,
                                   bi, bf, bo, bc);
    }

    // pred: 32768 warps, 8 warps/block
    fc_kernel<<<(B_ * S_) / 8, 256>>>(fcW, fcb, out);
    finalize_kernel<<<(B_ * H_ + 255) / 256, 256>>>(out, out_size);
}

// round 3
// speedup vs baseline: 1.3169x; 1.3169x over previous
#include <cuda_runtime.h>
#include <math.h>

#define B_ 64
#define S_ 512
#define D_ 512
#define H_ 1024

#define SA_STRIDE 66   // [kk][b] rows, even (float2 align), minor store conflicts ok
#define SW_STRIDE 36   // [kk][h*4+g] rows, mult of 4 (float4 align)
#define NC1 16         // x-phase chunks (512/32)
#define NC  48         // total chunks (512/32 + 1024/32)

// Scratch (device globals: allocation-free rule)
__device__ float g_H[2][B_ * H_];
__device__ float g_C[B_ * H_];
__device__ float g_outs[(size_t)S_ * B_ * H_];   // [s][b][h]

// ---------------------------------------------------------------------------
__global__ void lstm_init(const float* __restrict__ H0, const float* __restrict__ C0) {
    int i = blockIdx.x * blockDim.x + threadIdx.x;
    if (i < B_ * H_) {
        g_H[0][i] = H0[i];
        g_C[i]    = C0[i];
    }
}

__device__ __forceinline__ float sigmoidf_(float x) {
    return 1.0f / (1.0f + expf(-x));
}

// ---------------------------------------------------------------------------
// One fused LSTM step.
// Grid: 128 CTAs (8 h-columns each), 256 threads (8 warps/SM, 2/SMSP).
// Thread owns 2 batches x 1 h x 4 gates = 8 fp32 accumulators.
// smem: A transposed [kk][b] (LDS.64/k), W interleaved [kk][h][gate] (LDS.128/k)
// -> inner loop = 8 FFMA : 2 LDS. Double-buffered, 1 syncthreads per 32-k chunk.
// ---------------------------------------------------------------------------
__global__ void __launch_bounds__(256, 1) lstm_step(
    const float* __restrict__ x, int s, int cur,
    const float* __restrict__ Wxi, const float* __restrict__ Wxf,
    const float* __restrict__ Wxo, const float* __restrict__ Wxc,
    const float* __restrict__ Whi, const float* __restrict__ Whf,
    const float* __restrict__ Who, const float* __restrict__ Whc,
    const float* __restrict__ bi,  const float* __restrict__ bf,
    const float* __restrict__ bo,  const float* __restrict__ bc)
{
    __shared__ __align__(16) float sA[2][32 * SA_STRIDE];
    __shared__ __align__(16) float sW[2][32 * SW_STRIDE];

    const int t  = threadIdx.x;
    const int h0 = blockIdx.x * 8;

    // loader coordinates
    const int g   = t >> 6;          // gate 0..3
    const int kkw = (t >> 1) & 31;   // 0..31
    const int q   = t & 1;           // which half of the 8 h-cols

    // compute coordinates
    const int hloc = t & 7;          // 0..7
    const int b2   = (t >> 3) * 2;   // even batch index

    // per-thread gate weight pointers (phase 1 = Wx, phase 2 = Wh)
    const float* W1 = (g == 0) ? Wxi : (g == 1) ? Wxf : (g == 2) ? Wxo : Wxc;
    const float* W2 = (g == 0) ? Whi : (g == 1) ? Whf : (g == 2) ? Who : Whc;

    const float* xrow = x + (size_t)s * D_;          // + b * (S_*D_)
    const float* Hrow = g_H[cur];                    // + b * H_

    float4 pa0, pa1, pw;

    // prefetch chunk c into registers
    auto prefetch = [&](int c) {
        const float* Ab; size_t astr; const float* W; int k0;
        if (c < NC1) { Ab = xrow; astr = (size_t)S_ * D_; W = W1; k0 = c * 32; }
        else         { Ab = Hrow; astr = H_;              W = W2; k0 = (c - NC1) * 32; }
        {
            int idx = t;            // i = 0
            int bb = idx >> 3, c4 = idx & 7;
            pa0 = *(const float4*)(Ab + (size_t)bb * astr + k0 + c4 * 4);
        }
        {
            int idx = t + 256;      // i = 1
            int bb = idx >> 3, c4 = idx & 7;
            pa1 = *(const float4*)(Ab + (size_t)bb * astr + k0 + c4 * 4);
        }
        pw = *(const float4*)(W + (size_t)(k0 + kkw) * H_ + h0 + q * 4);
    };

    auto store_buf = [&](int buf) {
        {
            int idx = t;
            int bb = idx >> 3, c4 = idx & 7;
            sA[buf][(c4 * 4 + 0) * SA_STRIDE + bb] = pa0.x;
            sA[buf][(c4 * 4 + 1) * SA_STRIDE + bb] = pa0.y;
            sA[buf][(c4 * 4 + 2) * SA_STRIDE + bb] = pa0.z;
            sA[buf][(c4 * 4 + 3) * SA_STRIDE + bb] = pa0.w;
        }
        {
            int idx = t + 256;
            int bb = idx >> 3, c4 = idx & 7;
            sA[buf][(c4 * 4 + 0) * SA_STRIDE + bb] = pa1.x;
            sA[buf][(c4 * 4 + 1) * SA_STRIDE + bb] = pa1.y;
            sA[buf][(c4 * 4 + 2) * SA_STRIDE + bb] = pa1.z;
            sA[buf][(c4 * 4 + 3) * SA_STRIDE + bb] = pa1.w;
        }
        sW[buf][kkw * SW_STRIDE + (q * 4 + 0) * 4 + g] = pw.x;
        sW[buf][kkw * SW_STRIDE + (q * 4 + 1) * 4 + g] = pw.y;
        sW[buf][kkw * SW_STRIDE + (q * 4 + 2) * 4 + g] = pw.z;
        sW[buf][kkw * SW_STRIDE + (q * 4 + 3) * 4 + g] = pw.w;
    };

    float acc00 = 0.f, acc01 = 0.f, acc02 = 0.f, acc03 = 0.f;
    float acc10 = 0.f, acc11 = 0.f, acc12 = 0.f, acc13 = 0.f;

    prefetch(0);
    store_buf(0);
    __syncthreads();

    for (int c = 0; c < NC; c++) {
        const int buf = c & 1;
        if (c + 1 < NC) prefetch(c + 1);

        const float* __restrict__ pA = &sA[buf][b2];
        const float* __restrict__ pW = &sW[buf][hloc * 4];
#pragma unroll
        for (int kk = 0; kk < 32; kk++) {
            float2 a = *(const float2*)(pA + kk * SA_STRIDE);
            float4 w = *(const float4*)(pW + kk * SW_STRIDE);
            acc00 += a.x * w.x;  acc01 += a.x * w.y;  acc02 += a.x * w.z;  acc03 += a.x * w.w;
            acc10 += a.y * w.x;  acc11 += a.y * w.y;  acc12 += a.y * w.z;  acc13 += a.y * w.w;
        }

        if (c + 1 < NC) {
            store_buf(buf ^ 1);
            __syncthreads();
        }
    }

    // ---- Epilogue: 2 batches, 1 h column, 4 gates each ----
    const int h = h0 + hloc;
    const float bvi = bi[h], bvf = bf[h], bvo = bo[h], bvc = bc[h];

    float* Hn_next = g_H[cur ^ 1];

    {   // batch b2
        float iv = sigmoidf_(acc00 + bvi);
        float fv = sigmoidf_(acc01 + bvf);
        float ov = sigmoidf_(acc02 + bvo);
        float cv = tanhf(acc03 + bvc);
        float cn = fv * g_C[b2 * H_ + h] + iv * cv;
        float hn = ov * tanhf(cn);
        g_C[b2 * H_ + h] = cn;
        Hn_next[b2 * H_ + h] = hn;
        g_outs[((size_t)s * B_ + b2) * H_ + h] = hn;
    }
    {   // batch b2+1
        int b = b2 + 1;
        float iv = sigmoidf_(acc10 + bvi);
        float fv = sigmoidf_(acc11 + bvf);
        float ov = sigmoidf_(acc12 + bvo);
        float cv = tanhf(acc13 + bvc);
        float cn = fv * g_C[b * H_ + h] + iv * cv;
        float hn = ov * tanhf(cn);
        g_C[b * H_ + h] = cn;
        Hn_next[b * H_ + h] = hn;
        g_outs[((size_t)s * B_ + b) * H_ + h] = hn;
    }
}

// ---------------------------------------------------------------------------
// fc: pred[b,s] = outs[s][b][:] . fc_W + fc_b   (one warp per (s,b))
// ---------------------------------------------------------------------------
__global__ void fc_kernel(const float* __restrict__ fcW,
                          const float* __restrict__ fcb,
                          float* __restrict__ pred)
{
    int gw   = (blockIdx.x * blockDim.x + threadIdx.x) >> 5;
    int lane = threadIdx.x & 31;
    if (gw >= B_ * S_) return;
    int s = gw >> 6;
    int b = gw & 63;
    const float* row = g_outs + ((size_t)s * B_ + b) * H_;
    float sum = 0.0f;
#pragma unroll 4
    for (int hcol = lane; hcol < H_; hcol += 32)
        sum += row[hcol] * fcW[hcol];
#pragma unroll
    for (int o = 16; o; o >>= 1)
        sum += __shfl_down_sync(0xFFFFFFFFu, sum, o);
    if (lane == 0)
        pred[(size_t)b * S_ + s] = sum + fcb[0];
}

// ---------------------------------------------------------------------------
__global__ void finalize_kernel(float* __restrict__ out, int out_size) {
    int i = blockIdx.x * blockDim.x + threadIdx.x;
    if (i >= B_ * H_) return;
    const int PRED = B_ * S_;
    if (out_size >= PRED + B_ * H_)
        out[PRED + i] = g_H[0][i];      // after 512 steps final H sits in buffer 0
    if (out_size >= PRED + 2 * B_ * H_)
        out[PRED + B_ * H_ + i] = g_C[i];
}

// ---------------------------------------------------------------------------
extern "C" void kernel_launch(void* const* d_in, const int* in_sizes, int n_in,
                              void* d_out, int out_size)
{
    const float* inputs = (const float*)d_in[0];
    const float* H0     = (const float*)d_in[1];
    const float* C0     = (const float*)d_in[2];
    const float* Wxi = (const float*)d_in[3];
    const float* Whi = (const float*)d_in[4];
    const float* bi  = (const float*)d_in[5];
    const float* Wxf = (const float*)d_in[6];
    const float* Whf = (const float*)d_in[7];
    const float* bf  = (const float*)d_in[8];
    const float* Wxo = (const float*)d_in[9];
    const float* Who = (const float*)d_in[10];
    const float* bo  = (const float*)d_in[11];
    const float* Wxc = (const float*)d_in[12];
    const float* Whc = (const float*)d_in[13];
    const float* bc  = (const float*)d_in[14];
    const float* fcW = (const float*)d_in[15];
    const float* fcb = (const float*)d_in[16];
    float* out = (float*)d_out;

    lstm_init<<<(B_ * H_ + 255) / 256, 256>>>(H0, C0);

    for (int s = 0; s < S_; s++) {
        lstm_step<<<H_ / 8, 256>>>(inputs, s, s & 1,
                                   Wxi, Wxf, Wxo, Wxc,
                                   Whi, Whf, Who, Whc,
                                   bi, bf, bo, bc);
    }

    fc_kernel<<<(B_ * S_) / 8, 256>>>(fcW, fcb, out);
    finalize_kernel<<<(B_ * H_ + 255) / 256, 256>>>(out, out_size);
}

// round 5
// speedup vs baseline: 3.4042x; 2.5849x over previous
#include <cuda_runtime.h>
#include <cuda_bf16.h>
#include <math.h>
#include <stdint.h>

#define B_ 64
#define S_ 512
#define D_ 512
#define H_ 1024
#define KTOT 1536
#define NB   24            // K blocks of 64
#define NB1  8             // blocks covering x (512/64)
#define KB   64
#define NCTA 128           // each CTA: N=32 (8 h x 4 gates), M=64
#define ASTR 144           // A smem row stride bytes (72 bf16)
#define GSTR 33            // gate smem row stride floats

// dynamic smem offsets
#define SM_A(buf,half) (((buf)*2+(half))*9216)          // 64*144 = 9216 B each
#define SM_B(buf,half) (36864 + ((buf)*2+(half))*4608)  // 32*144 = 4608 B each
#define SM_G           55296                            // 64*33*4 = 8448 B
#define SMEM_TOTAL     63744

// ---------------- device scratch (allocation-free rule) -------------------
__device__ __nv_bfloat16 g_xhi[(size_t)S_ * B_ * D_];   // [s][b][d]
__device__ __nv_bfloat16 g_xlo[(size_t)S_ * B_ * D_];
__device__ __nv_bfloat16 g_Bhi[(size_t)4096 * KTOT];    // [n=h*4+g][k]
__device__ __nv_bfloat16 g_Blo[(size_t)4096 * KTOT];
__device__ __nv_bfloat16 g_Hhi[2][B_ * H_];
__device__ __nv_bfloat16 g_Hlo[2][B_ * H_];
__device__ float g_C[B_ * H_];
__device__ float g_outs[(size_t)S_ * B_ * H_];          // [s][b][h]

// ---------------- helpers ---------------------------------------------------
__device__ __forceinline__ uint32_t smem_u32(const void* p) {
    uint32_t a;
    asm("{ .reg .u64 t; cvta.to.shared.u64 t, %1; cvt.u32.u64 %0, t; }" : "=r"(a) : "l"(p));
    return a;
}
__device__ __forceinline__ void ldm4(uint32_t* r, uint32_t addr) {
    asm volatile("ldmatrix.sync.aligned.m8n8.x4.shared.b16 {%0,%1,%2,%3}, [%4];"
                 : "=r"(r[0]), "=r"(r[1]), "=r"(r[2]), "=r"(r[3]) : "r"(addr));
}
__device__ __forceinline__ void mma16816(float* d, const uint32_t* a, uint32_t b0, uint32_t b1) {
    asm volatile(
        "mma.sync.aligned.m16n8k16.row.col.f32.bf16.bf16.f32 "
        "{%0,%1,%2,%3}, {%4,%5,%6,%7}, {%8,%9}, {%0,%1,%2,%3};"
        : "+f"(d[0]), "+f"(d[1]), "+f"(d[2]), "+f"(d[3])
        : "r"(a[0]), "r"(a[1]), "r"(a[2]), "r"(a[3]), "r"(b0), "r"(b1));
}
__device__ __forceinline__ float sigmoidf_(float x) { return 1.0f / (1.0f + expf(-x)); }
__device__ __forceinline__ void split_bf16(float v, __nv_bfloat16& hi, __nv_bfloat16& lo) {
    hi = __float2bfloat16_rn(v);
    lo = __float2bfloat16_rn(v - __bfloat162float(hi));
}

// ---------------- conversion / init kernels --------------------------------
__global__ void conv_x(const float* __restrict__ x) {
    size_t n = (size_t)S_ * B_ * D_;
    for (size_t i = blockIdx.x * (size_t)blockDim.x + threadIdx.x; i < n;
         i += (size_t)gridDim.x * blockDim.x) {
        size_t s = i / (B_ * D_);
        size_t r = i % (B_ * D_);
        size_t b = r / D_, d = r % D_;
        split_bf16(x[(b * S_ + s) * D_ + d], g_xhi[i], g_xlo[i]);
    }
}

__global__ void conv_W(const float* __restrict__ Wxi, const float* __restrict__ Wxf,
                       const float* __restrict__ Wxo, const float* __restrict__ Wxc,
                       const float* __restrict__ Whi, const float* __restrict__ Whf,
                       const float* __restrict__ Who, const float* __restrict__ Whc) {
    size_t n = (size_t)4096 * KTOT;
    for (size_t i = blockIdx.x * (size_t)blockDim.x + threadIdx.x; i < n;
         i += (size_t)gridDim.x * blockDim.x) {
        size_t nn = i / KTOT, k = i % KTOT;
        int h = (int)(nn >> 2), g = (int)(nn & 3);
        const float* W;
        size_t off;
        if (k < D_) {
            W = (g == 0) ? Wxi : (g == 1) ? Wxf : (g == 2) ? Wxo : Wxc;
            off = k * H_ + h;
        } else {
            W = (g == 0) ? Whi : (g == 1) ? Whf : (g == 2) ? Who : Whc;
            off = (k - D_) * H_ + h;
        }
        split_bf16(W[off], g_Bhi[i], g_Blo[i]);
    }
}

__global__ void lstm_init(const float* __restrict__ H0, const float* __restrict__ C0) {
    int i = blockIdx.x * blockDim.x + threadIdx.x;
    if (i < B_ * H_) {
        split_bf16(H0[i], g_Hhi[0][i], g_Hlo[0][i]);
        g_C[i] = C0[i];
    }
}

// ---------------- fused LSTM step (mma.sync, split-bf16 x3) -----------------
__global__ void __launch_bounds__(256, 1) lstm_step(
    int s, int cur,
    const float* __restrict__ bi, const float* __restrict__ bf,
    const float* __restrict__ bo, const float* __restrict__ bc)
{
    extern __shared__ __align__(128) char smem[];
    const uint32_t sb = smem_u32(smem);
    const int t    = threadIdx.x;
    const int w    = t >> 5;
    const int lane = t & 31;

    // warp tile coordinates
    const int m0    = (w & 3) * 16;
    const int nloc0 = (w >> 2) * 16;

    // ldmatrix per-lane offsets (bytes, within a tile)
    const int frow = (lane & 7) + ((lane & 8) ? 8 : 0);
    const int fk   = (lane & 16) ? 16 : 0;
    const uint32_t aoff = (uint32_t)((m0 + frow) * ASTR + fk);
    const uint32_t boff = (uint32_t)((nloc0 + frow) * ASTR + fk);

    const __nv_bfloat16* Hh = g_Hhi[cur];
    const __nv_bfloat16* Hl = g_Hlo[cur];
    const size_t xoff = (size_t)s * B_ * D_;
    const int n0 = blockIdx.x * 32;

    // gmem prefetch registers
    uint4 pa0h, pa0l, pa1h, pa1l, pbh, pbl;

    const int arow0 = t >> 3,          ac16 = t & 7;
    const int arow1 = (t + 256) >> 3;
    const int brow  = t >> 3,          bc16 = t & 7;   // brow 0..31

    auto prefetch = [&](int c) {
        if (c < NB1) {
            const size_t k0 = (size_t)c * KB;
            const __nv_bfloat16* xh = g_xhi + xoff + k0 + ac16 * 8;
            const __nv_bfloat16* xl = g_xlo + xoff + k0 + ac16 * 8;
            pa0h = *(const uint4*)(xh + (size_t)arow0 * D_);
            pa0l = *(const uint4*)(xl + (size_t)arow0 * D_);
            pa1h = *(const uint4*)(xh + (size_t)arow1 * D_);
            pa1l = *(const uint4*)(xl + (size_t)arow1 * D_);
        } else {
            const int k0 = (c - NB1) * KB;
            const __nv_bfloat16* hh = Hh + k0 + ac16 * 8;
            const __nv_bfloat16* hl = Hl + k0 + ac16 * 8;
            pa0h = *(const uint4*)(hh + arow0 * H_);
            pa0l = *(const uint4*)(hl + arow0 * H_);
            pa1h = *(const uint4*)(hh + arow1 * H_);
            pa1l = *(const uint4*)(hl + arow1 * H_);
        }
        const size_t goff = (size_t)(n0 + brow) * KTOT + c * KB + bc16 * 8;
        pbh = *(const uint4*)(g_Bhi + goff);
        pbl = *(const uint4*)(g_Blo + goff);
    };

    auto store_buf = [&](int buf) {
        const int ao0 = arow0 * ASTR + ac16 * 16;
        const int ao1 = arow1 * ASTR + ac16 * 16;
        *(uint4*)(smem + SM_A(buf, 0) + ao0) = pa0h;
        *(uint4*)(smem + SM_A(buf, 1) + ao0) = pa0l;
        *(uint4*)(smem + SM_A(buf, 0) + ao1) = pa1h;
        *(uint4*)(smem + SM_A(buf, 1) + ao1) = pa1l;
        const int bo = brow * ASTR + bc16 * 16;
        *(uint4*)(smem + SM_B(buf, 0) + bo) = pbh;
        *(uint4*)(smem + SM_B(buf, 1) + bo) = pbl;
    };

    float acc[8];
#pragma unroll
    for (int i = 0; i < 8; i++) acc[i] = 0.0f;

    prefetch(0);
    store_buf(0);
    __syncthreads();

    for (int c = 0; c < NB; c++) {
        const int buf = c & 1;
        if (c + 1 < NB) prefetch(c + 1);

        const uint32_t ah_base = sb + SM_A(buf, 0) + aoff;
        const uint32_t al_base = sb + SM_A(buf, 1) + aoff;
        const uint32_t bh_base = sb + SM_B(buf, 0) + boff;
        const uint32_t bl_base = sb + SM_B(buf, 1) + boff;

#pragma unroll
        for (int ks = 0; ks < 4; ks++) {
            uint32_t a_hi[4], a_lo[4], b_hi[4], b_lo[4];
            ldm4(a_hi, ah_base + ks * 32);
            ldm4(b_hi, bh_base + ks * 32);
            ldm4(a_lo, al_base + ks * 32);
            ldm4(b_lo, bl_base + ks * 32);
            mma16816(acc,     a_hi, b_hi[0], b_hi[2]);
            mma16816(acc + 4, a_hi, b_hi[1], b_hi[3]);
            mma16816(acc,     a_hi, b_lo[0], b_lo[2]);
            mma16816(acc + 4, a_hi, b_lo[1], b_lo[3]);
            mma16816(acc,     a_lo, b_hi[0], b_hi[2]);
            mma16816(acc + 4, a_lo, b_hi[1], b_hi[3]);
        }

        if (c + 1 < NB) {
            __syncthreads();       // everyone done reading buf^1 (block c-1)
            store_buf(buf ^ 1);
            __syncthreads();       // block c+1 visible before anyone computes it
        }
    }

    // ---- epilogue: C fragments -> smem gates -> cell update ----
    float* sg = (float*)(smem + SM_G);
    {
        const int r0 = m0 + (lane >> 2);
        const int c0 = nloc0 + 2 * (lane & 3);
        sg[r0 * GSTR + c0]           = acc[0];
        sg[r0 * GSTR + c0 + 1]       = acc[1];
        sg[(r0 + 8) * GSTR + c0]     = acc[2];
        sg[(r0 + 8) * GSTR + c0 + 1] = acc[3];
        sg[r0 * GSTR + c0 + 8]       = acc[4];
        sg[r0 * GSTR + c0 + 9]       = acc[5];
        sg[(r0 + 8) * GSTR + c0 + 8] = acc[6];
        sg[(r0 + 8) * GSTR + c0 + 9] = acc[7];
    }
    __syncthreads();

    __nv_bfloat16* Hnh = g_Hhi[cur ^ 1];
    __nv_bfloat16* Hnl = g_Hlo[cur ^ 1];
#pragma unroll
    for (int j = 0; j < 2; j++) {
        const int idx  = t + j * 256;
        const int b    = idx >> 3;
        const int hloc = idx & 7;
        const int h    = blockIdx.x * 8 + hloc;
        const float* gr = sg + b * GSTR + hloc * 4;
        float iv = sigmoidf_(gr[0] + bi[h]);
        float fv = sigmoidf_(gr[1] + bf[h]);
        float ov = sigmoidf_(gr[2] + bo[h]);
        float cv = tanhf(gr[3] + bc[h]);
        float cn = fv * g_C[b * H_ + h] + iv * cv;
        float hn = ov * tanhf(cn);
        g_C[b * H_ + h] = cn;
        g_outs[((size_t)s * B_ + b) * H_ + h] = hn;
        __nv_bfloat16 hh, hl;
        split_bf16(hn, hh, hl);
        Hnh[b * H_ + h] = hh;
        Hnl[b * H_ + h] = hl;
    }
}

// ---------------- fc + finalize --------------------------------------------
__global__ void fc_kernel(const float* __restrict__ fcW,
                          const float* __restrict__ fcb,
                          float* __restrict__ pred)
{
    int gw = (blockIdx.x * blockDim.x + threadIdx.x) >> 5;
    int lane = threadIdx.x & 31;
    if (gw >= B_ * S_) return;
    int s = gw >> 6;
    int b = gw & 63;
    const float* row = g_outs + ((size_t)s * B_ + b) * H_;
    float sum = 0.0f;
#pragma unroll 4
    for (int h = lane; h < H_; h += 32) sum += row[h] * fcW[h];
#pragma unroll
    for (int o = 16; o; o >>= 1) sum += __shfl_down_sync(0xFFFFFFFFu, sum, o);
    if (lane == 0) pred[(size_t)b * S_ + s] = sum + fcb[0];
}

__global__ void finalize_kernel(float* __restrict__ out, int out_size) {
    int i = blockIdx.x * blockDim.x + threadIdx.x;
    if (i >= B_ * H_) return;
    const int PRED = B_ * S_;
    if (out_size >= PRED + B_ * H_)
        out[PRED + i] = g_outs[((size_t)(S_ - 1) * B_) * H_ + i];
    if (out_size >= PRED + 2 * B_ * H_)
        out[PRED + B_ * H_ + i] = g_C[i];
}

// ---------------------------------------------------------------------------
extern "C" void kernel_launch(void* const* d_in, const int* in_sizes, int n_in,
                              void* d_out, int out_size)
{
    const float* inputs = (const float*)d_in[0];
    const float* H0  = (const float*)d_in[1];
    const float* C0  = (const float*)d_in[2];
    const float* Wxi = (const float*)d_in[3];
    const float* Whi = (const float*)d_in[4];
    const float* bi  = (const float*)d_in[5];
    const float* Wxf = (const float*)d_in[6];
    const float* Whf = (const float*)d_in[7];
    const float* bf  = (const float*)d_in[8];
    const float* Wxo = (const float*)d_in[9];
    const float* Who = (const float*)d_in[10];
    const float* bo  = (const float*)d_in[11];
    const float* Wxc = (const float*)d_in[12];
    const float* Whc = (const float*)d_in[13];
    const float* bc  = (const float*)d_in[14];
    const float* fcW = (const float*)d_in[15];
    const float* fcb = (const float*)d_in[16];
    float* out = (float*)d_out;

    cudaFuncSetAttribute(lstm_step, cudaFuncAttributeMaxDynamicSharedMemorySize, SMEM_TOTAL);

    conv_x<<<4096, 256>>>(inputs);
    conv_W<<<3072, 256>>>(Wxi, Wxf, Wxo, Wxc, Whi, Whf, Who, Whc);
    lstm_init<<<(B_ * H_ + 255) / 256, 256>>>(H0, C0);

    for (int s = 0; s < S_; s++)
        lstm_step<<<NCTA, 256, SMEM_TOTAL>>>(s, s & 1, bi, bf, bo, bc);

    fc_kernel<<<(B_ * S_) / 8, 256>>>(fcW, fcb, out);
    finalize_kernel<<<(B_ * H_ + 255) / 256, 256>>>(out, out_size);
}